// round 4
// baseline (speedup 1.0000x reference)
#include <cuda_runtime.h>

typedef unsigned long long ull;

#define THREADS 256
#define BM 128
#define BK 32
#define BU 32
#define AP (BM + 4)   // As row pad
#define BP3 100       // Bs pad for 96 cols (3 gates)
#define BP2 68        // Bs pad for 64 cols (2 gates)

#define DH 256
#define NLEAF 16384
#define DIN 300

// ---------- packed fp32x2 helpers (sm_103a FFMA2 path, PTX-only) ----------
__device__ __forceinline__ ull pack2(float x) {
    ull r; asm("mov.b64 %0, {%1, %1};" : "=l"(r) : "f"(x)); return r;
}
__device__ __forceinline__ float2 unpack2(ull v) {
    float2 r; asm("mov.b64 {%0, %1}, %2;" : "=f"(r.x), "=f"(r.y) : "l"(v)); return r;
}
__device__ __forceinline__ void ffma2(ull& d, ull a, ull b) {
    asm("fma.rn.f32x2 %0, %1, %2, %0;" : "+l"(d) : "l"(a), "l"(b));
}
__device__ __forceinline__ float sigf(float x) { return 1.0f / (1.0f + expf(-x)); }

// ---------- scratch (device globals: no allocation allowed) ----------
__device__ float g_hA[NLEAF * DH];
__device__ float g_cA[NLEAF * DH];
__device__ float g_hB[(NLEAF / 2) * DH];
__device__ float g_cB[(NLEAF / 2) * DH];
__device__ float g_hl[(NLEAF / 2) * DH];
__device__ float g_cl[(NLEAF / 2) * DH];
__device__ float g_rc[DH];   // root cell (unused output)

// =====================================================================
// Leaf: gx = emb[ids] @ Wx + bx ; gi,go,cpre = split(gx)
// c = sig(gi)*tanh(cpre) ; h = sig(go)*tanh(c)
// Block: 128 leaves x 32 hidden units (x3 gate cols). Thread: 8 rows x 6 cols.
// =====================================================================
__global__ void __launch_bounds__(THREADS, 2)
leaf_kernel(const int* __restrict__ ids, const float* __restrict__ emb,
            const float* __restrict__ Wx, const float* __restrict__ bx)
{
    __shared__ float As[BK][AP];
    __shared__ float Bs[BK][BP3];
    __shared__ int rid[BM];

    const int tid = threadIdx.x;
    const int tx = tid & 15;
    const int ty = tid >> 4;
    const int m0 = blockIdx.x * BM;
    const int u0 = blockIdx.y * BU;

    if (tid < BM) rid[tid] = ids[m0 + tid];
    __syncthreads();

    ull acc[8][3];
#pragma unroll
    for (int r = 0; r < 8; r++)
#pragma unroll
        for (int g = 0; g < 3; g++) acc[r][g] = 0ull;

    for (int k0 = 0; k0 < DIN; k0 += BK) {
        const int klim = DIN - k0;   // >= BK except last chunk (12)
        // ---- stage A: 4 float4 per thread, transpose into As[k][m] ----
#pragma unroll
        for (int i = 0; i < 4; i++) {
            int idx = tid + i * THREADS;
            int m = idx >> 3;
            int kq = idx & 7;
            float4 v = make_float4(0.f, 0.f, 0.f, 0.f);
            if (kq * 4 < klim)
                v = *reinterpret_cast<const float4*>(&emb[(size_t)rid[m] * DIN + k0 + kq * 4]);
            As[kq * 4 + 0][m] = v.x;
            As[kq * 4 + 1][m] = v.y;
            As[kq * 4 + 2][m] = v.z;
            As[kq * 4 + 3][m] = v.w;
        }
        // ---- stage B: 3 float4 per thread ----
        {
            int kk = tid >> 3;
#pragma unroll
            for (int i = 0; i < 3; i++) {
                int c4 = (tid & 7) + i * 8;
                int g = c4 >> 3;
                int u4 = c4 & 7;
                float4 w = make_float4(0.f, 0.f, 0.f, 0.f);
                if (kk < klim)
                    w = *reinterpret_cast<const float4*>(
                        &Wx[(size_t)(k0 + kk) * 768 + g * 256 + u0 + u4 * 4]);
                *reinterpret_cast<float4*>(&Bs[kk][g * 32 + u4 * 4]) = w;
            }
        }
        __syncthreads();
#pragma unroll 8
        for (int kk = 0; kk < BK; kk++) {
            float4 a0 = *reinterpret_cast<const float4*>(&As[kk][ty * 8]);
            float4 a1 = *reinterpret_cast<const float4*>(&As[kk][ty * 8 + 4]);
            ull ap[8] = {pack2(a0.x), pack2(a0.y), pack2(a0.z), pack2(a0.w),
                         pack2(a1.x), pack2(a1.y), pack2(a1.z), pack2(a1.w)};
            ull b0 = *reinterpret_cast<const ull*>(&Bs[kk][tx * 2]);
            ull b1 = *reinterpret_cast<const ull*>(&Bs[kk][32 + tx * 2]);
            ull b2 = *reinterpret_cast<const ull*>(&Bs[kk][64 + tx * 2]);
#pragma unroll
            for (int r = 0; r < 8; r++) {
                ffma2(acc[r][0], ap[r], b0);
                ffma2(acc[r][1], ap[r], b1);
                ffma2(acc[r][2], ap[r], b2);
            }
        }
        __syncthreads();
    }

    const int u = u0 + tx * 2;
    const float2 bgi = make_float2(bx[u],       bx[u + 1]);
    const float2 bgo = make_float2(bx[256 + u], bx[256 + u + 1]);
    const float2 bcp = make_float2(bx[512 + u], bx[512 + u + 1]);
#pragma unroll
    for (int r = 0; r < 8; r++) {
        int row = m0 + ty * 8 + r;
        float2 gi = unpack2(acc[r][0]); gi.x += bgi.x; gi.y += bgi.y;
        float2 go = unpack2(acc[r][1]); go.x += bgo.x; go.y += bgo.y;
        float2 cp = unpack2(acc[r][2]); cp.x += bcp.x; cp.y += bcp.y;
        float cx = sigf(gi.x) * tanhf(cp.x);
        float cy = sigf(gi.y) * tanhf(cp.y);
        float hx = sigf(go.x) * tanhf(cx);
        float hy = sigf(go.y) * tanhf(cy);
        *reinterpret_cast<float2*>(&g_cA[(size_t)row * DH + u]) = make_float2(cx, cy);
        *reinterpret_cast<float2*>(&g_hA[(size_t)row * DH + u]) = make_float2(hx, hy);
    }
}

// =====================================================================
// Stage 1 per level: left child (sibling = None).
// g = h_even @ Wc + bc + bs ; only gc (cols 256:512) and go (512:768).
// cl = sig(gc)*c_even ; hl = sig(go)*tanh(cl)
// =====================================================================
__global__ void __launch_bounds__(THREADS, 2)
comb1_kernel(int src, const float* __restrict__ Wc,
             const float* __restrict__ bc, const float* __restrict__ bs,
             int Mout, float* __restrict__ root_out)
{
    const float* __restrict__ h_in = src ? g_hB : g_hA;
    const float* __restrict__ c_in = src ? g_cB : g_cA;
    float* __restrict__ hl_out = root_out ? root_out : g_hl;
    float* __restrict__ cl_out = root_out ? g_rc : g_cl;

    __shared__ float As[BK][AP];
    __shared__ float Bs[BK][BP2];

    const int tid = threadIdx.x;
    const int tx = tid & 15;
    const int ty = tid >> 4;
    const int m0 = blockIdx.x * BM;
    const int u0 = blockIdx.y * BU;

    ull acc[8][2];
#pragma unroll
    for (int r = 0; r < 8; r++) { acc[r][0] = 0ull; acc[r][1] = 0ull; }

    for (int k0 = 0; k0 < DH; k0 += BK) {
#pragma unroll
        for (int i = 0; i < 4; i++) {
            int idx = tid + i * THREADS;
            int m = idx >> 3;
            int kq = idx & 7;
            float4 v = make_float4(0.f, 0.f, 0.f, 0.f);
            if (m0 + m < Mout)
                v = *reinterpret_cast<const float4*>(
                    &h_in[(size_t)(2 * (m0 + m)) * DH + k0 + kq * 4]);
            As[kq * 4 + 0][m] = v.x;
            As[kq * 4 + 1][m] = v.y;
            As[kq * 4 + 2][m] = v.z;
            As[kq * 4 + 3][m] = v.w;
        }
        {
            int kk = tid >> 3;
#pragma unroll
            for (int i = 0; i < 2; i++) {
                int c4 = (tid & 7) + i * 8;
                int g = c4 >> 3;
                int u4 = c4 & 7;
                float4 w = *reinterpret_cast<const float4*>(
                    &Wc[(size_t)(k0 + kk) * 768 + 256 + g * 256 + u0 + u4 * 4]);
                *reinterpret_cast<float4*>(&Bs[kk][g * 32 + u4 * 4]) = w;
            }
        }
        __syncthreads();
#pragma unroll 8
        for (int kk = 0; kk < BK; kk++) {
            float4 a0 = *reinterpret_cast<const float4*>(&As[kk][ty * 8]);
            float4 a1 = *reinterpret_cast<const float4*>(&As[kk][ty * 8 + 4]);
            ull ap[8] = {pack2(a0.x), pack2(a0.y), pack2(a0.z), pack2(a0.w),
                         pack2(a1.x), pack2(a1.y), pack2(a1.z), pack2(a1.w)};
            ull b0 = *reinterpret_cast<const ull*>(&Bs[kk][tx * 2]);
            ull b1 = *reinterpret_cast<const ull*>(&Bs[kk][32 + tx * 2]);
#pragma unroll
            for (int r = 0; r < 8; r++) {
                ffma2(acc[r][0], ap[r], b0);
                ffma2(acc[r][1], ap[r], b1);
            }
        }
        __syncthreads();
    }

    const int u = u0 + tx * 2;
    const float2 bgc = make_float2(bc[256 + u] + bs[256 + u], bc[256 + u + 1] + bs[256 + u + 1]);
    const float2 bgo = make_float2(bc[512 + u] + bs[512 + u], bc[512 + u + 1] + bs[512 + u + 1]);
#pragma unroll
    for (int r = 0; r < 8; r++) {
        int row = m0 + ty * 8 + r;
        if (row < Mout) {
            float2 gc = unpack2(acc[r][0]); gc.x += bgc.x; gc.y += bgc.y;
            float2 go = unpack2(acc[r][1]); go.x += bgo.x; go.y += bgo.y;
            float2 cc = *reinterpret_cast<const float2*>(&c_in[(size_t)(2 * row) * DH + u]);
            float clx = sigf(gc.x) * cc.x;
            float cly = sigf(gc.y) * cc.y;
            float hlx = sigf(go.x) * tanhf(clx);
            float hly = sigf(go.y) * tanhf(cly);
            *reinterpret_cast<float2*>(&cl_out[(size_t)row * DH + u]) = make_float2(clx, cly);
            *reinterpret_cast<float2*>(&hl_out[(size_t)row * DH + u]) = make_float2(hlx, hly);
        }
    }
}

// =====================================================================
// Stage 2 per level: right child, sibling = stage-1 output.
// g = h_odd @ Wc + hl @ Ws + bc + bs  (K = 512 by concatenation)
// c' = sig(gc)*c_odd + sig(gs)*cl ; h' = sig(go)*tanh(c')
// =====================================================================
__global__ void __launch_bounds__(THREADS, 2)
comb2_kernel(int src, const float* __restrict__ Wc, const float* __restrict__ Ws,
             const float* __restrict__ bc, const float* __restrict__ bs, int Mout)
{
    const float* __restrict__ h_in = src ? g_hB : g_hA;
    const float* __restrict__ c_in = src ? g_cB : g_cA;
    float* __restrict__ h_out = src ? g_hA : g_hB;
    float* __restrict__ c_out = src ? g_cA : g_cB;

    __shared__ float As[BK][AP];
    __shared__ float Bs[BK][BP3];

    const int tid = threadIdx.x;
    const int tx = tid & 15;
    const int ty = tid >> 4;
    const int m0 = blockIdx.x * BM;
    const int u0 = blockIdx.y * BU;

    ull acc[8][3];
#pragma unroll
    for (int r = 0; r < 8; r++)
#pragma unroll
        for (int g = 0; g < 3; g++) acc[r][g] = 0ull;

    for (int k0 = 0; k0 < 2 * DH; k0 += BK) {
        const bool second = (k0 >= DH);
        const float* __restrict__ W = second ? Ws : Wc;
        const int kw = k0 & (DH - 1);
#pragma unroll
        for (int i = 0; i < 4; i++) {
            int idx = tid + i * THREADS;
            int m = idx >> 3;
            int kq = idx & 7;
            float4 v = make_float4(0.f, 0.f, 0.f, 0.f);
            if (m0 + m < Mout) {
                const float* src_row = second
                    ? &g_hl[(size_t)(m0 + m) * DH]
                    : &h_in[(size_t)(2 * (m0 + m) + 1) * DH];
                v = *reinterpret_cast<const float4*>(&src_row[kw + kq * 4]);
            }
            As[kq * 4 + 0][m] = v.x;
            As[kq * 4 + 1][m] = v.y;
            As[kq * 4 + 2][m] = v.z;
            As[kq * 4 + 3][m] = v.w;
        }
        {
            int kk = tid >> 3;
#pragma unroll
            for (int i = 0; i < 3; i++) {
                int c4 = (tid & 7) + i * 8;
                int g = c4 >> 3;
                int u4 = c4 & 7;
                float4 w = *reinterpret_cast<const float4*>(
                    &W[(size_t)(kw + kk) * 768 + g * 256 + u0 + u4 * 4]);
                *reinterpret_cast<float4*>(&Bs[kk][g * 32 + u4 * 4]) = w;
            }
        }
        __syncthreads();
#pragma unroll 8
        for (int kk = 0; kk < BK; kk++) {
            float4 a0 = *reinterpret_cast<const float4*>(&As[kk][ty * 8]);
            float4 a1 = *reinterpret_cast<const float4*>(&As[kk][ty * 8 + 4]);
            ull ap[8] = {pack2(a0.x), pack2(a0.y), pack2(a0.z), pack2(a0.w),
                         pack2(a1.x), pack2(a1.y), pack2(a1.z), pack2(a1.w)};
            ull b0 = *reinterpret_cast<const ull*>(&Bs[kk][tx * 2]);
            ull b1 = *reinterpret_cast<const ull*>(&Bs[kk][32 + tx * 2]);
            ull b2 = *reinterpret_cast<const ull*>(&Bs[kk][64 + tx * 2]);
#pragma unroll
            for (int r = 0; r < 8; r++) {
                ffma2(acc[r][0], ap[r], b0);
                ffma2(acc[r][1], ap[r], b1);
                ffma2(acc[r][2], ap[r], b2);
            }
        }
        __syncthreads();
    }

    const int u = u0 + tx * 2;
    const float2 bgs = make_float2(bc[u] + bs[u], bc[u + 1] + bs[u + 1]);
    const float2 bgc = make_float2(bc[256 + u] + bs[256 + u], bc[256 + u + 1] + bs[256 + u + 1]);
    const float2 bgo = make_float2(bc[512 + u] + bs[512 + u], bc[512 + u + 1] + bs[512 + u + 1]);
#pragma unroll
    for (int r = 0; r < 8; r++) {
        int row = m0 + ty * 8 + r;
        if (row < Mout) {
            float2 gs_ = unpack2(acc[r][0]); gs_.x += bgs.x; gs_.y += bgs.y;
            float2 gc  = unpack2(acc[r][1]); gc.x  += bgc.x; gc.y  += bgc.y;
            float2 go  = unpack2(acc[r][2]); go.x  += bgo.x; go.y  += bgo.y;
            float2 co = *reinterpret_cast<const float2*>(&c_in[(size_t)(2 * row + 1) * DH + u]);
            float2 cs = *reinterpret_cast<const float2*>(&g_cl[(size_t)row * DH + u]);
            float cnx = sigf(gc.x) * co.x + sigf(gs_.x) * cs.x;
            float cny = sigf(gc.y) * co.y + sigf(gs_.y) * cs.y;
            float hnx = sigf(go.x) * tanhf(cnx);
            float hny = sigf(go.y) * tanhf(cny);
            *reinterpret_cast<float2*>(&c_out[(size_t)row * DH + u]) = make_float2(cnx, cny);
            *reinterpret_cast<float2*>(&h_out[(size_t)row * DH + u]) = make_float2(hnx, hny);
        }
    }
}

// =====================================================================
extern "C" void kernel_launch(void* const* d_in, const int* in_sizes, int n_in,
                              void* d_out, int out_size)
{
    const int*   ids = (const int*)d_in[0];
    const float* emb = (const float*)d_in[1];
    const float* Wx  = (const float*)d_in[2];
    const float* bx  = (const float*)d_in[3];
    const float* Ws  = (const float*)d_in[4];
    const float* bs  = (const float*)d_in[5];
    const float* Wc  = (const float*)d_in[6];
    const float* bc  = (const float*)d_in[7];
    float* out = (float*)d_out;
    (void)in_sizes; (void)n_in; (void)out_size;

    leaf_kernel<<<dim3(NLEAF / BM, DH / BU), THREADS>>>(ids, emb, Wx, bx);

    int M = NLEAF;
    for (int l = 0; l < 14; l++) {
        int Mo = M >> 1;
        int src = l & 1;   // 0: read A (write B), 1: read B (write A)
        dim3 grid((Mo + BM - 1) / BM, DH / BU);
        comb1_kernel<<<grid, THREADS>>>(src, Wc, bc, bs, Mo, nullptr);
        comb2_kernel<<<grid, THREADS>>>(src, Wc, Ws, bc, bs, Mo);
        M = Mo;
    }
    // After 14 levels the single node sits in the A buffers (14 is even).
    comb1_kernel<<<dim3(1, DH / BU), THREADS>>>(0, Wc, bc, bs, 1, out);
}

// round 5
// speedup vs baseline: 1.0000x; 1.0000x over previous
#include <cuda_runtime.h>

typedef unsigned long long ull;

#define THREADS 256
#define BM 128
#define BK 32
#define BU 32
#define AP (BM + 4)   // As row pad
#define BP3 100       // Bs pad for 96 cols (3 gates)
#define BP2 68        // Bs pad for 64 cols (2 gates)

#define DH 256
#define NLEAF 16384
#define DIN 300

// ---------- packed fp32x2 helpers (sm_103a FFMA2 path, PTX-only) ----------
__device__ __forceinline__ ull pack2(float x) {
    ull r; asm("mov.b64 %0, {%1, %1};" : "=l"(r) : "f"(x)); return r;
}
__device__ __forceinline__ float2 unpack2(ull v) {
    float2 r; asm("mov.b64 {%0, %1}, %2;" : "=f"(r.x), "=f"(r.y) : "l"(v)); return r;
}
__device__ __forceinline__ void ffma2(ull& d, ull a, ull b) {
    asm("fma.rn.f32x2 %0, %1, %2, %0;" : "+l"(d) : "l"(a), "l"(b));
}
__device__ __forceinline__ float sigf(float x) { return 1.0f / (1.0f + expf(-x)); }

// ---------- scratch (device globals: no allocation allowed) ----------
__device__ float g_hA[NLEAF * DH];
__device__ float g_cA[NLEAF * DH];
__device__ float g_hB[(NLEAF / 2) * DH];
__device__ float g_cB[(NLEAF / 2) * DH];
__device__ float g_hl[(NLEAF / 2) * DH];
__device__ float g_cl[(NLEAF / 2) * DH];
__device__ float g_rc[DH];   // root cell (unused output)

// =====================================================================
// Leaf: gx = emb[ids] @ Wx + bx ; gi,go,cpre = split(gx)
// c = sig(gi)*tanh(cpre) ; h = sig(go)*tanh(c)
// Block: 128 leaves x 32 hidden units (x3 gate cols). Thread: 8 rows x 6 cols.
// =====================================================================
__global__ void __launch_bounds__(THREADS, 2)
leaf_kernel(const int* __restrict__ ids, const float* __restrict__ emb,
            const float* __restrict__ Wx, const float* __restrict__ bx)
{
    __shared__ float As[BK][AP];
    __shared__ float Bs[BK][BP3];
    __shared__ int rid[BM];

    const int tid = threadIdx.x;
    const int tx = tid & 15;
    const int ty = tid >> 4;
    const int m0 = blockIdx.x * BM;
    const int u0 = blockIdx.y * BU;

    if (tid < BM) rid[tid] = ids[m0 + tid];
    __syncthreads();

    ull acc[8][3];
#pragma unroll
    for (int r = 0; r < 8; r++)
#pragma unroll
        for (int g = 0; g < 3; g++) acc[r][g] = 0ull;

    for (int k0 = 0; k0 < DIN; k0 += BK) {
        const int klim = DIN - k0;   // >= BK except last chunk (12)
        // ---- stage A: 4 float4 per thread, transpose into As[k][m] ----
#pragma unroll
        for (int i = 0; i < 4; i++) {
            int idx = tid + i * THREADS;
            int m = idx >> 3;
            int kq = idx & 7;
            float4 v = make_float4(0.f, 0.f, 0.f, 0.f);
            if (kq * 4 < klim)
                v = *reinterpret_cast<const float4*>(&emb[(size_t)rid[m] * DIN + k0 + kq * 4]);
            As[kq * 4 + 0][m] = v.x;
            As[kq * 4 + 1][m] = v.y;
            As[kq * 4 + 2][m] = v.z;
            As[kq * 4 + 3][m] = v.w;
        }
        // ---- stage B: 3 float4 per thread ----
        {
            int kk = tid >> 3;
#pragma unroll
            for (int i = 0; i < 3; i++) {
                int c4 = (tid & 7) + i * 8;
                int g = c4 >> 3;
                int u4 = c4 & 7;
                float4 w = make_float4(0.f, 0.f, 0.f, 0.f);
                if (kk < klim)
                    w = *reinterpret_cast<const float4*>(
                        &Wx[(size_t)(k0 + kk) * 768 + g * 256 + u0 + u4 * 4]);
                *reinterpret_cast<float4*>(&Bs[kk][g * 32 + u4 * 4]) = w;
            }
        }
        __syncthreads();
#pragma unroll 8
        for (int kk = 0; kk < BK; kk++) {
            float4 a0 = *reinterpret_cast<const float4*>(&As[kk][ty * 8]);
            float4 a1 = *reinterpret_cast<const float4*>(&As[kk][ty * 8 + 4]);
            ull ap[8] = {pack2(a0.x), pack2(a0.y), pack2(a0.z), pack2(a0.w),
                         pack2(a1.x), pack2(a1.y), pack2(a1.z), pack2(a1.w)};
            ull b0 = *reinterpret_cast<const ull*>(&Bs[kk][tx * 2]);
            ull b1 = *reinterpret_cast<const ull*>(&Bs[kk][32 + tx * 2]);
            ull b2 = *reinterpret_cast<const ull*>(&Bs[kk][64 + tx * 2]);
#pragma unroll
            for (int r = 0; r < 8; r++) {
                ffma2(acc[r][0], ap[r], b0);
                ffma2(acc[r][1], ap[r], b1);
                ffma2(acc[r][2], ap[r], b2);
            }
        }
        __syncthreads();
    }

    const int u = u0 + tx * 2;
    const float2 bgi = make_float2(bx[u],       bx[u + 1]);
    const float2 bgo = make_float2(bx[256 + u], bx[256 + u + 1]);
    const float2 bcp = make_float2(bx[512 + u], bx[512 + u + 1]);
#pragma unroll
    for (int r = 0; r < 8; r++) {
        int row = m0 + ty * 8 + r;
        float2 gi = unpack2(acc[r][0]); gi.x += bgi.x; gi.y += bgi.y;
        float2 go = unpack2(acc[r][1]); go.x += bgo.x; go.y += bgo.y;
        float2 cp = unpack2(acc[r][2]); cp.x += bcp.x; cp.y += bcp.y;
        float cx = sigf(gi.x) * tanhf(cp.x);
        float cy = sigf(gi.y) * tanhf(cp.y);
        float hx = sigf(go.x) * tanhf(cx);
        float hy = sigf(go.y) * tanhf(cy);
        *reinterpret_cast<float2*>(&g_cA[(size_t)row * DH + u]) = make_float2(cx, cy);
        *reinterpret_cast<float2*>(&g_hA[(size_t)row * DH + u]) = make_float2(hx, hy);
    }
}

// =====================================================================
// Stage 1 per level: left child (sibling = None).
// g = h_even @ Wc + bc + bs ; only gc (cols 256:512) and go (512:768).
// cl = sig(gc)*c_even ; hl = sig(go)*tanh(cl)
// =====================================================================
__global__ void __launch_bounds__(THREADS, 2)
comb1_kernel(int src, const float* __restrict__ Wc,
             const float* __restrict__ bc, const float* __restrict__ bs,
             int Mout, float* __restrict__ root_out)
{
    const float* __restrict__ h_in = src ? g_hB : g_hA;
    const float* __restrict__ c_in = src ? g_cB : g_cA;
    float* __restrict__ hl_out = root_out ? root_out : g_hl;
    float* __restrict__ cl_out = root_out ? g_rc : g_cl;

    __shared__ float As[BK][AP];
    __shared__ float Bs[BK][BP2];

    const int tid = threadIdx.x;
    const int tx = tid & 15;
    const int ty = tid >> 4;
    const int m0 = blockIdx.x * BM;
    const int u0 = blockIdx.y * BU;

    ull acc[8][2];
#pragma unroll
    for (int r = 0; r < 8; r++) { acc[r][0] = 0ull; acc[r][1] = 0ull; }

    for (int k0 = 0; k0 < DH; k0 += BK) {
#pragma unroll
        for (int i = 0; i < 4; i++) {
            int idx = tid + i * THREADS;
            int m = idx >> 3;
            int kq = idx & 7;
            float4 v = make_float4(0.f, 0.f, 0.f, 0.f);
            if (m0 + m < Mout)
                v = *reinterpret_cast<const float4*>(
                    &h_in[(size_t)(2 * (m0 + m)) * DH + k0 + kq * 4]);
            As[kq * 4 + 0][m] = v.x;
            As[kq * 4 + 1][m] = v.y;
            As[kq * 4 + 2][m] = v.z;
            As[kq * 4 + 3][m] = v.w;
        }
        {
            int kk = tid >> 3;
#pragma unroll
            for (int i = 0; i < 2; i++) {
                int c4 = (tid & 7) + i * 8;
                int g = c4 >> 3;
                int u4 = c4 & 7;
                float4 w = *reinterpret_cast<const float4*>(
                    &Wc[(size_t)(k0 + kk) * 768 + 256 + g * 256 + u0 + u4 * 4]);
                *reinterpret_cast<float4*>(&Bs[kk][g * 32 + u4 * 4]) = w;
            }
        }
        __syncthreads();
#pragma unroll 8
        for (int kk = 0; kk < BK; kk++) {
            float4 a0 = *reinterpret_cast<const float4*>(&As[kk][ty * 8]);
            float4 a1 = *reinterpret_cast<const float4*>(&As[kk][ty * 8 + 4]);
            ull ap[8] = {pack2(a0.x), pack2(a0.y), pack2(a0.z), pack2(a0.w),
                         pack2(a1.x), pack2(a1.y), pack2(a1.z), pack2(a1.w)};
            ull b0 = *reinterpret_cast<const ull*>(&Bs[kk][tx * 2]);
            ull b1 = *reinterpret_cast<const ull*>(&Bs[kk][32 + tx * 2]);
#pragma unroll
            for (int r = 0; r < 8; r++) {
                ffma2(acc[r][0], ap[r], b0);
                ffma2(acc[r][1], ap[r], b1);
            }
        }
        __syncthreads();
    }

    const int u = u0 + tx * 2;
    const float2 bgc = make_float2(bc[256 + u] + bs[256 + u], bc[256 + u + 1] + bs[256 + u + 1]);
    const float2 bgo = make_float2(bc[512 + u] + bs[512 + u], bc[512 + u + 1] + bs[512 + u + 1]);
#pragma unroll
    for (int r = 0; r < 8; r++) {
        int row = m0 + ty * 8 + r;
        if (row < Mout) {
            float2 gc = unpack2(acc[r][0]); gc.x += bgc.x; gc.y += bgc.y;
            float2 go = unpack2(acc[r][1]); go.x += bgo.x; go.y += bgo.y;
            float2 cc = *reinterpret_cast<const float2*>(&c_in[(size_t)(2 * row) * DH + u]);
            float clx = sigf(gc.x) * cc.x;
            float cly = sigf(gc.y) * cc.y;
            float hlx = sigf(go.x) * tanhf(clx);
            float hly = sigf(go.y) * tanhf(cly);
            *reinterpret_cast<float2*>(&cl_out[(size_t)row * DH + u]) = make_float2(clx, cly);
            *reinterpret_cast<float2*>(&hl_out[(size_t)row * DH + u]) = make_float2(hlx, hly);
        }
    }
}

// =====================================================================
// Stage 2 per level: right child, sibling = stage-1 output.
// g = h_odd @ Wc + hl @ Ws + bc + bs  (K = 512 by concatenation)
// c' = sig(gc)*c_odd + sig(gs)*cl ; h' = sig(go)*tanh(c')
// =====================================================================
__global__ void __launch_bounds__(THREADS, 2)
comb2_kernel(int src, const float* __restrict__ Wc, const float* __restrict__ Ws,
             const float* __restrict__ bc, const float* __restrict__ bs, int Mout)
{
    const float* __restrict__ h_in = src ? g_hB : g_hA;
    const float* __restrict__ c_in = src ? g_cB : g_cA;
    float* __restrict__ h_out = src ? g_hA : g_hB;
    float* __restrict__ c_out = src ? g_cA : g_cB;

    __shared__ float As[BK][AP];
    __shared__ float Bs[BK][BP3];

    const int tid = threadIdx.x;
    const int tx = tid & 15;
    const int ty = tid >> 4;
    const int m0 = blockIdx.x * BM;
    const int u0 = blockIdx.y * BU;

    ull acc[8][3];
#pragma unroll
    for (int r = 0; r < 8; r++)
#pragma unroll
        for (int g = 0; g < 3; g++) acc[r][g] = 0ull;

    for (int k0 = 0; k0 < 2 * DH; k0 += BK) {
        const bool second = (k0 >= DH);
        const float* __restrict__ W = second ? Ws : Wc;
        const int kw = k0 & (DH - 1);
#pragma unroll
        for (int i = 0; i < 4; i++) {
            int idx = tid + i * THREADS;
            int m = idx >> 3;
            int kq = idx & 7;
            float4 v = make_float4(0.f, 0.f, 0.f, 0.f);
            if (m0 + m < Mout) {
                const float* src_row = second
                    ? &g_hl[(size_t)(m0 + m) * DH]
                    : &h_in[(size_t)(2 * (m0 + m) + 1) * DH];
                v = *reinterpret_cast<const float4*>(&src_row[kw + kq * 4]);
            }
            As[kq * 4 + 0][m] = v.x;
            As[kq * 4 + 1][m] = v.y;
            As[kq * 4 + 2][m] = v.z;
            As[kq * 4 + 3][m] = v.w;
        }
        {
            int kk = tid >> 3;
#pragma unroll
            for (int i = 0; i < 3; i++) {
                int c4 = (tid & 7) + i * 8;
                int g = c4 >> 3;
                int u4 = c4 & 7;
                float4 w = *reinterpret_cast<const float4*>(
                    &W[(size_t)(kw + kk) * 768 + g * 256 + u0 + u4 * 4]);
                *reinterpret_cast<float4*>(&Bs[kk][g * 32 + u4 * 4]) = w;
            }
        }
        __syncthreads();
#pragma unroll 8
        for (int kk = 0; kk < BK; kk++) {
            float4 a0 = *reinterpret_cast<const float4*>(&As[kk][ty * 8]);
            float4 a1 = *reinterpret_cast<const float4*>(&As[kk][ty * 8 + 4]);
            ull ap[8] = {pack2(a0.x), pack2(a0.y), pack2(a0.z), pack2(a0.w),
                         pack2(a1.x), pack2(a1.y), pack2(a1.z), pack2(a1.w)};
            ull b0 = *reinterpret_cast<const ull*>(&Bs[kk][tx * 2]);
            ull b1 = *reinterpret_cast<const ull*>(&Bs[kk][32 + tx * 2]);
            ull b2 = *reinterpret_cast<const ull*>(&Bs[kk][64 + tx * 2]);
#pragma unroll
            for (int r = 0; r < 8; r++) {
                ffma2(acc[r][0], ap[r], b0);
                ffma2(acc[r][1], ap[r], b1);
                ffma2(acc[r][2], ap[r], b2);
            }
        }
        __syncthreads();
    }

    const int u = u0 + tx * 2;
    const float2 bgs = make_float2(bc[u] + bs[u], bc[u + 1] + bs[u + 1]);
    const float2 bgc = make_float2(bc[256 + u] + bs[256 + u], bc[256 + u + 1] + bs[256 + u + 1]);
    const float2 bgo = make_float2(bc[512 + u] + bs[512 + u], bc[512 + u + 1] + bs[512 + u + 1]);
#pragma unroll
    for (int r = 0; r < 8; r++) {
        int row = m0 + ty * 8 + r;
        if (row < Mout) {
            float2 gs_ = unpack2(acc[r][0]); gs_.x += bgs.x; gs_.y += bgs.y;
            float2 gc  = unpack2(acc[r][1]); gc.x  += bgc.x; gc.y  += bgc.y;
            float2 go  = unpack2(acc[r][2]); go.x  += bgo.x; go.y  += bgo.y;
            float2 co = *reinterpret_cast<const float2*>(&c_in[(size_t)(2 * row + 1) * DH + u]);
            float2 cs = *reinterpret_cast<const float2*>(&g_cl[(size_t)row * DH + u]);
            float cnx = sigf(gc.x) * co.x + sigf(gs_.x) * cs.x;
            float cny = sigf(gc.y) * co.y + sigf(gs_.y) * cs.y;
            float hnx = sigf(go.x) * tanhf(cnx);
            float hny = sigf(go.y) * tanhf(cny);
            *reinterpret_cast<float2*>(&c_out[(size_t)row * DH + u]) = make_float2(cnx, cny);
            *reinterpret_cast<float2*>(&h_out[(size_t)row * DH + u]) = make_float2(hnx, hny);
        }
    }
}

// =====================================================================
extern "C" void kernel_launch(void* const* d_in, const int* in_sizes, int n_in,
                              void* d_out, int out_size)
{
    const int*   ids = (const int*)d_in[0];
    const float* emb = (const float*)d_in[1];
    const float* Wx  = (const float*)d_in[2];
    const float* bx  = (const float*)d_in[3];
    const float* Ws  = (const float*)d_in[4];
    const float* bs  = (const float*)d_in[5];
    const float* Wc  = (const float*)d_in[6];
    const float* bc  = (const float*)d_in[7];
    float* out = (float*)d_out;
    (void)in_sizes; (void)n_in; (void)out_size;

    leaf_kernel<<<dim3(NLEAF / BM, DH / BU), THREADS>>>(ids, emb, Wx, bx);

    int M = NLEAF;
    for (int l = 0; l < 14; l++) {
        int Mo = M >> 1;
        int src = l & 1;   // 0: read A (write B), 1: read B (write A)
        dim3 grid((Mo + BM - 1) / BM, DH / BU);
        comb1_kernel<<<grid, THREADS>>>(src, Wc, bc, bs, Mo, nullptr);
        comb2_kernel<<<grid, THREADS>>>(src, Wc, Ws, bc, bs, Mo);
        M = Mo;
    }
    // After 14 levels the single node sits in the A buffers (14 is even).
    comb1_kernel<<<dim3(1, DH / BU), THREADS>>>(0, Wc, bc, bs, 1, out);
}

// round 7
// speedup vs baseline: 1.4499x; 1.4498x over previous
#include <cuda_runtime.h>
#include <cuda_bf16.h>
#include <cstdint>

#define DH 256
#define NLEAF 16384

__device__ __forceinline__ float sigf(float x) { return 1.0f / (1.0f + __expf(-x)); }
__device__ __forceinline__ void split2(float x, float y, uint32_t& hi, uint32_t& lo) {
    __nv_bfloat16 hx = __float2bfloat16(x), hy = __float2bfloat16(y);
    __nv_bfloat162 hp; hp.x = hx; hp.y = hy;
    hi = *reinterpret_cast<uint32_t*>(&hp);
    __nv_bfloat162 lp = __floats2bfloat162_rn(x - __bfloat162float(hx), y - __bfloat162float(hy));
    lo = *reinterpret_cast<uint32_t*>(&lp);
}
// D += A * B  (m16n8k16, bf16 in, fp32 acc)
__device__ __forceinline__ void mma16816(float* d, const uint32_t* a, uint32_t b0, uint32_t b1) {
    asm volatile("mma.sync.aligned.m16n8k16.row.col.f32.bf16.bf16.f32 "
        "{%0,%1,%2,%3}, {%4,%5,%6,%7}, {%8,%9}, {%0,%1,%2,%3};"
        : "+f"(d[0]), "+f"(d[1]), "+f"(d[2]), "+f"(d[3])
        : "r"(a[0]), "r"(a[1]), "r"(a[2]), "r"(a[3]), "r"(b0), "r"(b1));
}

// ---------------- scratch ----------------
__device__ float g_hA[NLEAF * DH];
__device__ float g_cA[NLEAF * DH];
__device__ float g_hB[(NLEAF / 2) * DH];
__device__ float g_cB[(NLEAF / 2) * DH];
__device__ float g_hl[(NLEAF / 2) * DH];
__device__ float g_cl[(NLEAF / 2) * DH];

// =====================================================================
// Tensor-core kernel. MODE: 0=leaf (gates gi/go/cpre, K=300 from emb),
// 1=comb1 (left child; gates gc/go; K=256 from h_even),
// 2=comb2 (right child; gates gs/gc/go; K=512 over [h_odd ; hl]).
// Block: 128 rows x 64 hidden units. 8 warps = 4(m) x 2(n).
// fp32 emulated as bf16 hi+lo, 3 HMMA passes, fp32 accumulators.
// =====================================================================
template <int MODE>
__global__ void __launch_bounds__(256)
tree_mma(int src, const int* __restrict__ ids, const float* __restrict__ emb,
         const float* __restrict__ Wm, const float* __restrict__ Ws2,
         const float* __restrict__ b0v, const float* __restrict__ b1v)
{
    constexpr int NG = (MODE == 1) ? 2 : 3;
    constexpr int NC = (MODE == 0) ? 10 : ((MODE == 1) ? 8 : 16);

    __shared__ uint32_t Ah[128][17], Al[128][17];          // [row][kpair]
    __shared__ uint32_t Bh[NG][64][17], Bl[NG][64][17];    // [gate][n][kpair]
    __shared__ float sbias[NG * 64];
    __shared__ int sI[128];

    const int tid = threadIdx.x;
    const int lane = tid & 31, wid = tid >> 5;
    const int wm = wid & 3, wn = wid >> 2;
    const int g8 = lane >> 2, tig = lane & 3;
    const int m0 = blockIdx.x * 128, u0 = blockIdx.y * 64;

    if (MODE == 0 && tid < 128) sI[tid] = ids[m0 + tid];
    if (tid < NG * 64) {
        int col = (MODE == 1 ? 256 : 0) + (tid >> 6) * 256 + u0 + (tid & 63);
        float b = b0v[col];
        if (MODE) b += b1v[col];
        sbias[tid] = b;
    }

    const float* __restrict__ h_in = src ? g_hB : g_hA;
    const float* __restrict__ c_in = src ? g_cB : g_cA;
    float* __restrict__ h_out = src ? g_hA : g_hB;
    float* __restrict__ c_out = src ? g_cA : g_cB;

    float acc[NG][2][4][4];
#pragma unroll
    for (int g = 0; g < NG; g++)
#pragma unroll
        for (int mt = 0; mt < 2; mt++)
#pragma unroll
            for (int nt = 0; nt < 4; nt++)
#pragma unroll
                for (int e = 0; e < 4; e++) acc[g][mt][nt][e] = 0.0f;

    __syncthreads();

    for (int c = 0; c < NC; c++) {
        // ---- stage A: 128 x 32 fp32 -> hi/lo bf16 pairs ----
#pragma unroll
        for (int i = 0; i < 4; i++) {
            int idx = tid + i * 256;
            int r = idx >> 3, k4 = (idx & 7) << 2;
            float4 v;
            if (MODE == 0) {
                int kg = c * 32 + k4;
                v = (kg < 300) ? *(const float4*)&emb[(size_t)sI[r] * 300 + kg]
                               : make_float4(0.f, 0.f, 0.f, 0.f);
            } else if (MODE == 1) {
                v = *(const float4*)&h_in[(size_t)(2 * (m0 + r)) * DH + c * 32 + k4];
            } else {
                v = (c < 8) ? *(const float4*)&h_in[(size_t)(2 * (m0 + r) + 1) * DH + c * 32 + k4]
                            : *(const float4*)&g_hl[(size_t)(m0 + r) * DH + (c - 8) * 32 + k4];
            }
            uint32_t h01, l01, h23, l23;
            split2(v.x, v.y, h01, l01);
            split2(v.z, v.w, h23, l23);
            int kp = k4 >> 1;
            Ah[r][kp] = h01; Ah[r][kp + 1] = h23;
            Al[r][kp] = l01; Al[r][kp + 1] = l23;
        }
        // ---- stage B: per gate, transpose W[k][col] -> Bs[n][kpair] ----
        const float* __restrict__ W = (MODE == 2 && c >= 8) ? Ws2 : Wm;
        const int kb = (MODE == 2) ? ((c & 7) * 32) : c * 32;
        const int n = tid & 63;
#pragma unroll
        for (int g = 0; g < NG; g++) {
            int colb = (MODE == 1 ? 256 : 0) + g * 256 + u0 + n;
#pragma unroll
            for (int i = 0; i < 4; i++) {
                int kp = (tid >> 6) + i * 4;
                int k = kb + 2 * kp;
                float v0 = 0.f, v1 = 0.f;
                if (MODE != 0 || k < 300)     v0 = W[(size_t)k * 768 + colb];
                if (MODE != 0 || k + 1 < 300) v1 = W[(size_t)(k + 1) * 768 + colb];
                uint32_t hi, lo;
                split2(v0, v1, hi, lo);
                Bh[g][n][kp] = hi;
                Bl[g][n][kp] = lo;
            }
        }
        __syncthreads();
        // ---- compute: two k16 steps per chunk ----
#pragma unroll
        for (int s = 0; s < 2; s++) {
            const int kp0 = tig + 8 * s;
            uint32_t aH[2][4], aL[2][4];
#pragma unroll
            for (int mt = 0; mt < 2; mt++) {
                int row = wm * 32 + mt * 16 + g8;
                aH[mt][0] = Ah[row][kp0];     aH[mt][1] = Ah[row + 8][kp0];
                aH[mt][2] = Ah[row][kp0 + 4]; aH[mt][3] = Ah[row + 8][kp0 + 4];
                aL[mt][0] = Al[row][kp0];     aL[mt][1] = Al[row + 8][kp0];
                aL[mt][2] = Al[row][kp0 + 4]; aL[mt][3] = Al[row + 8][kp0 + 4];
            }
#pragma unroll
            for (int g = 0; g < NG; g++) {
#pragma unroll
                for (int nt = 0; nt < 4; nt++) {
                    int nn = wn * 32 + nt * 8 + g8;
                    uint32_t bH0 = Bh[g][nn][kp0], bH1 = Bh[g][nn][kp0 + 4];
                    uint32_t bL0 = Bl[g][nn][kp0], bL1 = Bl[g][nn][kp0 + 4];
#pragma unroll
                    for (int mt = 0; mt < 2; mt++) {
                        mma16816(acc[g][mt][nt], aH[mt], bH0, bH1);
                        mma16816(acc[g][mt][nt], aH[mt], bL0, bL1);
                        mma16816(acc[g][mt][nt], aL[mt], bH0, bH1);
                    }
                }
            }
        }
        __syncthreads();
    }

    // ---- fused epilogue straight from accumulators ----
#pragma unroll
    for (int mt = 0; mt < 2; mt++) {
        int rowb = m0 + wm * 32 + mt * 16 + g8;
#pragma unroll
        for (int nt = 0; nt < 4; nt++) {
            int nl = wn * 32 + nt * 8 + tig * 2;
            int u = u0 + nl;
#pragma unroll
            for (int half = 0; half < 2; half++) {
                int r = rowb + half * 8;
                int e = half * 2;
                float a0x = acc[0][mt][nt][e],     a0y = acc[0][mt][nt][e + 1];
                float a1x = acc[1][mt][nt][e],     a1y = acc[1][mt][nt][e + 1];
                if (MODE == 0) {
                    float gix = a0x + sbias[nl],       giy = a0y + sbias[nl + 1];
                    float gox = a1x + sbias[64 + nl],  goy = a1y + sbias[64 + nl + 1];
                    float cpx = acc[2][mt][nt][e]     + sbias[128 + nl];
                    float cpy = acc[2][mt][nt][e + 1] + sbias[128 + nl + 1];
                    float cx = sigf(gix) * tanhf(cpx), cy = sigf(giy) * tanhf(cpy);
                    float hx = sigf(gox) * tanhf(cx),  hy = sigf(goy) * tanhf(cy);
                    *(float2*)&g_cA[(size_t)r * DH + u] = make_float2(cx, cy);
                    *(float2*)&g_hA[(size_t)r * DH + u] = make_float2(hx, hy);
                } else if (MODE == 1) {
                    float gcx = a0x + sbias[nl],      gcy = a0y + sbias[nl + 1];
                    float gox = a1x + sbias[64 + nl], goy = a1y + sbias[64 + nl + 1];
                    float2 cc = *(const float2*)&c_in[(size_t)(2 * r) * DH + u];
                    float clx = sigf(gcx) * cc.x, cly = sigf(gcy) * cc.y;
                    float hlx = sigf(gox) * tanhf(clx), hly = sigf(goy) * tanhf(cly);
                    *(float2*)&g_cl[(size_t)r * DH + u] = make_float2(clx, cly);
                    *(float2*)&g_hl[(size_t)r * DH + u] = make_float2(hlx, hly);
                } else {
                    float gsx = a0x + sbias[nl],       gsy = a0y + sbias[nl + 1];
                    float gcx = a1x + sbias[64 + nl],  gcy = a1y + sbias[64 + nl + 1];
                    float gox = acc[2][mt][nt][e]     + sbias[128 + nl];
                    float goy = acc[2][mt][nt][e + 1] + sbias[128 + nl + 1];
                    float2 co = *(const float2*)&c_in[(size_t)(2 * r + 1) * DH + u];
                    float2 cs = *(const float2*)&g_cl[(size_t)r * DH + u];
                    float cnx = sigf(gcx) * co.x + sigf(gsx) * cs.x;
                    float cny = sigf(gcy) * co.y + sigf(gsy) * cs.y;
                    float hnx = sigf(gox) * tanhf(cnx), hny = sigf(goy) * tanhf(cny);
                    *(float2*)&c_out[(size_t)r * DH + u] = make_float2(cnx, cny);
                    *(float2*)&h_out[(size_t)r * DH + u] = make_float2(hnx, hny);
                }
            }
        }
    }
}

// =====================================================================
// Small levels (Mout < 128): one block per node, thread = hidden unit.
// Exact fp32. stage 1 = left combine (also root), 2 = right combine.
// =====================================================================
__global__ void __launch_bounds__(256, 1)
comb_small(int src, int stage, const float* __restrict__ Wc, const float* __restrict__ Ws,
           const float* __restrict__ bc, const float* __restrict__ bs,
           float* __restrict__ root_out)
{
    __shared__ float sh[512];
    const int node = blockIdx.x, tid = threadIdx.x;
    const float* __restrict__ h_in = src ? g_hB : g_hA;
    const float* __restrict__ c_in = src ? g_cB : g_cA;
    float* __restrict__ h_out = src ? g_hA : g_hB;
    float* __restrict__ c_out = src ? g_cA : g_cB;

    if (stage == 1) {
        sh[tid] = h_in[(size_t)(2 * node) * DH + tid];
        __syncthreads();
        float gc = bc[256 + tid] + bs[256 + tid];
        float go = bc[512 + tid] + bs[512 + tid];
#pragma unroll 8
        for (int k = 0; k < DH; k++) {
            float h = sh[k];
            gc += h * Wc[(size_t)k * 768 + 256 + tid];
            go += h * Wc[(size_t)k * 768 + 512 + tid];
        }
        float cl = sigf(gc) * c_in[(size_t)(2 * node) * DH + tid];
        float hl = sigf(go) * tanhf(cl);
        g_cl[(size_t)node * DH + tid] = cl;
        if (root_out) root_out[tid] = hl;
        else g_hl[(size_t)node * DH + tid] = hl;
    } else {
        sh[tid] = h_in[(size_t)(2 * node + 1) * DH + tid];
        sh[256 + tid] = g_hl[(size_t)node * DH + tid];
        __syncthreads();
        float gs = bc[tid] + bs[tid];
        float gc = bc[256 + tid] + bs[256 + tid];
        float go = bc[512 + tid] + bs[512 + tid];
#pragma unroll 4
        for (int k = 0; k < DH; k++) {
            float ho = sh[k], hs = sh[256 + k];
            gs += ho * Wc[(size_t)k * 768 + tid]       + hs * Ws[(size_t)k * 768 + tid];
            gc += ho * Wc[(size_t)k * 768 + 256 + tid] + hs * Ws[(size_t)k * 768 + 256 + tid];
            go += ho * Wc[(size_t)k * 768 + 512 + tid] + hs * Ws[(size_t)k * 768 + 512 + tid];
        }
        float cn = sigf(gc) * c_in[(size_t)(2 * node + 1) * DH + tid] +
                   sigf(gs) * g_cl[(size_t)node * DH + tid];
        float hn = sigf(go) * tanhf(cn);
        c_out[(size_t)node * DH + tid] = cn;
        h_out[(size_t)node * DH + tid] = hn;
    }
}

// =====================================================================
extern "C" void kernel_launch(void* const* d_in, const int* in_sizes, int n_in,
                              void* d_out, int out_size)
{
    const int*   ids = (const int*)d_in[0];
    const float* emb = (const float*)d_in[1];
    const float* Wx  = (const float*)d_in[2];
    const float* bx  = (const float*)d_in[3];
    const float* Ws  = (const float*)d_in[4];
    const float* bs  = (const float*)d_in[5];
    const float* Wc  = (const float*)d_in[6];
    const float* bc  = (const float*)d_in[7];
    float* out = (float*)d_out;
    (void)in_sizes; (void)n_in; (void)out_size;

    // leaf: gx = emb[ids] @ Wx + bx  -> h,c into A buffers
    tree_mma<0><<<dim3(NLEAF / 128, 4), 256>>>(0, ids, emb, Wx, nullptr, bx, nullptr);

    int M = NLEAF;
    for (int l = 0; l < 14; l++) {
        int Mo = M >> 1;
        int src = l & 1;   // 0: read A / write B ; 1: read B / write A
        if (Mo >= 128) {
            dim3 grid(Mo / 128, 4);
            tree_mma<1><<<grid, 256>>>(src, nullptr, nullptr, Wc, nullptr, bc, bs);
            tree_mma<2><<<grid, 256>>>(src, nullptr, nullptr, Wc, Ws, bc, bs);
        } else {
            comb_small<<<Mo, 256>>>(src, 1, Wc, Ws, bc, bs, nullptr);
            comb_small<<<Mo, 256>>>(src, 2, Wc, Ws, bc, bs, nullptr);
        }
        M = Mo;
    }
    // root: sibling = zeros -> stage-1 math; level 14 state is in A buffers
    comb_small<<<1, 256>>>(0, 1, Wc, Ws, bc, bs, out);
}